// round 3
// baseline (speedup 1.0000x reference)
#include <cuda_runtime.h>

// NeuralODEClassifier, split into two kernels to cut register pressure:
//  K1: 63 Euler steps of tanh-MLP(2->64->2)  -> writes yT to __device__ scratch
//  K2: classifier 2->64->64->3 on yT
//
// tanh(z) = 1 - 2/(2^(C*z)+1), C = 2*log2(e);  W1/b1 pre-scaled by C and
// the (1 - 2r) fold absorbed into W2 (sW2n = -2*W2, sS = colsum(W2)+b2).

#define H 64
#define TT 64
#define NCLS 3
#define BLOCK 128
#define BMAX 65536

__device__ float g_yT[BMAX * 2];

__device__ __forceinline__ float fast_ex2(float x) {
    float r; asm("ex2.approx.f32 %0, %1;" : "=f"(r) : "f"(x)); return r;
}
__device__ __forceinline__ float fast_rcp(float x) {
    float r; asm("rcp.approx.f32 %0, %1;" : "=f"(r) : "f"(x)); return r;
}

// ---------------------------------------------------------------- K1: ODE ---
__global__ __launch_bounds__(BLOCK, 4)
void node_ode_kernel(
    const float* __restrict__ y0g,  const float* __restrict__ tg,
    const float* __restrict__ W1,   const float* __restrict__ b1,
    const float* __restrict__ W2,   const float* __restrict__ b2,
    int B)
{
    __shared__ __align__(16) float sW1zA[H];     // W1 row 0 * C
    __shared__ __align__(16) float sW1zB[H];     // W1 row 1 * C
    __shared__ __align__(16) float sb1z[H];      // b1 * C
    __shared__ __align__(16) float4 sW2n[H / 2]; // -2*W2 pairs {j:(c0,c1), j+1:(c0,c1)}
    __shared__ float sS[2];                      // colsum(W2) + b2
    __shared__ float sdt[TT - 1];

    const float C = 2.88539008177792681472f;     // 2*log2(e)
    const int tid = threadIdx.x;

    if (tid < H) {
        sW1zA[tid] = W1[tid] * C;
        sW1zB[tid] = W1[H + tid] * C;
        sb1z[tid]  = b1[tid] * C;
    }
    if (tid >= H && tid < H + H / 2) {
        int p = tid - H;
        int j4 = p * 4;
        sW2n[p] = make_float4(-2.0f * W2[j4 + 0], -2.0f * W2[j4 + 1],
                              -2.0f * W2[j4 + 2], -2.0f * W2[j4 + 3]);
    }
    if (tid >= H + H / 2 && tid < H + H / 2 + 2) {
        int c = tid - (H + H / 2);
        float s = b2[c];
        #pragma unroll 8
        for (int j = 0; j < H; j++) s += W2[j * 2 + c];
        sS[c] = s;
    }
    if (tid < TT - 1) sdt[tid] = tg[tid + 1] - tg[tid];
    __syncthreads();

    const int idx = blockIdx.x * BLOCK + tid;
    if (idx >= B) return;

    float ya = y0g[idx * 2 + 0];
    float yb = y0g[idx * 2 + 1];
    const float S0 = sS[0], S1 = sS[1];

    for (int s = 0; s < TT - 1; s++) {
        const float dt = sdt[s];
        // 4 partial accumulators per output to break the FMA dependence chain
        float a0_0 = 0.f, a0_1 = 0.f, a0_2 = 0.f, a0_3 = 0.f;
        float a1_0 = 0.f, a1_1 = 0.f, a1_2 = 0.f, a1_3 = 0.f;
        #pragma unroll
        for (int j = 0; j < H; j += 4) {
            const float4 wa = *(const float4*)&sW1zA[j];
            const float4 wb = *(const float4*)&sW1zB[j];
            const float4 bb = *(const float4*)&sb1z[j];
            const float4 v0 = sW2n[j / 2];
            const float4 v1 = sW2n[j / 2 + 1];

            float w0 = fmaf(ya, wa.x, fmaf(yb, wb.x, bb.x));
            float w1 = fmaf(ya, wa.y, fmaf(yb, wb.y, bb.y));
            float w2 = fmaf(ya, wa.z, fmaf(yb, wb.z, bb.z));
            float w3 = fmaf(ya, wa.w, fmaf(yb, wb.w, bb.w));

            float r0 = fast_rcp(fast_ex2(w0) + 1.0f);
            float r1 = fast_rcp(fast_ex2(w1) + 1.0f);
            float r2 = fast_rcp(fast_ex2(w2) + 1.0f);
            float r3 = fast_rcp(fast_ex2(w3) + 1.0f);

            a0_0 = fmaf(r0, v0.x, a0_0); a1_0 = fmaf(r0, v0.y, a1_0);
            a0_1 = fmaf(r1, v0.z, a0_1); a1_1 = fmaf(r1, v0.w, a1_1);
            a0_2 = fmaf(r2, v1.x, a0_2); a1_2 = fmaf(r2, v1.y, a1_2);
            a0_3 = fmaf(r3, v1.z, a0_3); a1_3 = fmaf(r3, v1.w, a1_3);
        }
        float acc0 = (a0_0 + a0_1) + (a0_2 + a0_3);
        float acc1 = (a1_0 + a1_1) + (a1_2 + a1_3);
        ya = fmaf(dt, S0 + acc0, ya);
        yb = fmaf(dt, S1 + acc1, yb);
    }

    g_yT[idx * 2 + 0] = ya;
    g_yT[idx * 2 + 1] = yb;
}

// --------------------------------------------------------- K2: classifier ---
__global__ __launch_bounds__(BLOCK, 4)
void node_cls_kernel(
    const float* __restrict__ Wc1,  const float* __restrict__ bc1,
    const float* __restrict__ Wc2,  const float* __restrict__ bc2,
    const float* __restrict__ Wc3,  const float* __restrict__ bc3,
    float* __restrict__ out, int B)
{
    __shared__ __align__(16) float sWc1A[H];
    __shared__ __align__(16) float sWc1B[H];
    __shared__ __align__(16) float sbc1[H];
    __shared__ __align__(16) float sWc2T[H][H];  // transposed: [out_j][in_k]
    __shared__ __align__(16) float sbc2[H];
    __shared__ __align__(16) float4 sWc3[H];     // padded rows {w0,w1,w2,0}
    __shared__ float sbc3[NCLS];

    const int tid = threadIdx.x;
    if (tid < H) {
        sWc1A[tid] = Wc1[tid];
        sWc1B[tid] = Wc1[H + tid];
        sbc1[tid]  = bc1[tid];
        sbc2[tid]  = bc2[tid];
        sWc3[tid]  = make_float4(Wc3[tid * 3 + 0], Wc3[tid * 3 + 1],
                                 Wc3[tid * 3 + 2], 0.0f);
    }
    if (tid < NCLS) sbc3[tid] = bc3[tid];
    for (int i = tid; i < H * H; i += BLOCK) {
        int k = i >> 6, j = i & 63;
        sWc2T[j][k] = Wc2[i];
    }
    __syncthreads();

    const int idx = blockIdx.x * BLOCK + tid;
    if (idx >= B) return;

    const float ya = g_yT[idx * 2 + 0];
    const float yb = g_yT[idx * 2 + 1];

    float h1[H];
    #pragma unroll
    for (int j = 0; j < H; j++)
        h1[j] = fmaxf(fmaf(ya, sWc1A[j], fmaf(yb, sWc1B[j], sbc1[j])), 0.0f);

    float o0 = sbc3[0], o1 = sbc3[1], o2 = sbc3[2];
    for (int j = 0; j < H; j++) {
        float s0 = sbc2[j], s1 = 0.f, s2 = 0.f, s3 = 0.f;
        #pragma unroll
        for (int k = 0; k < H; k += 4) {
            const float4 w = *(const float4*)&sWc2T[j][k];
            s0 = fmaf(h1[k + 0], w.x, s0);
            s1 = fmaf(h1[k + 1], w.y, s1);
            s2 = fmaf(h1[k + 2], w.z, s2);
            s3 = fmaf(h1[k + 3], w.w, s3);
        }
        float s = fmaxf((s0 + s1) + (s2 + s3), 0.0f);
        const float4 wc = sWc3[j];
        o0 = fmaf(s, wc.x, o0);
        o1 = fmaf(s, wc.y, o1);
        o2 = fmaf(s, wc.z, o2);
    }

    out[idx * 3 + 0] = o0;
    out[idx * 3 + 1] = o1;
    out[idx * 3 + 2] = o2;
}

extern "C" void kernel_launch(void* const* d_in, const int* in_sizes, int n_in,
                              void* d_out, int out_size) {
    const float* y0  = (const float*)d_in[0];
    const float* t   = (const float*)d_in[1];
    const float* W1  = (const float*)d_in[2];
    const float* b1  = (const float*)d_in[3];
    const float* W2  = (const float*)d_in[4];
    const float* b2  = (const float*)d_in[5];
    const float* Wc1 = (const float*)d_in[6];
    const float* bc1 = (const float*)d_in[7];
    const float* Wc2 = (const float*)d_in[8];
    const float* bc2 = (const float*)d_in[9];
    const float* Wc3 = (const float*)d_in[10];
    const float* bc3 = (const float*)d_in[11];
    float* out = (float*)d_out;

    const int B = in_sizes[0] / 2;
    const int grid = (B + BLOCK - 1) / BLOCK;
    node_ode_kernel<<<grid, BLOCK>>>(y0, t, W1, b1, W2, b2, B);
    node_cls_kernel<<<grid, BLOCK>>>(Wc1, bc1, Wc2, bc2, Wc3, bc3, out, B);
}